// round 1
// baseline (speedup 1.0000x reference)
#include <cuda_runtime.h>
#include <math.h>

#define MAX_B 64

// Per-image sum accumulator (double for safety across 2.76M-element sums).
__device__ double g_sum[MAX_B];

__global__ void zero_sums_kernel() {
    int i = threadIdx.x;
    if (i < MAX_B) g_sum[i] = 0.0;
}

// Grid: (blocksPerImage, B). Each block reduces a slice of one image with
// float4 loads, tree-reduces in shared, one double atomicAdd per block.
__global__ void reduce_mean_kernel(const float* __restrict__ im, int chw) {
    const int b = blockIdx.y;
    const int n4 = chw >> 2;                 // chw divisible by 4 (W=1280)
    const float4* __restrict__ p = reinterpret_cast<const float4*>(im) + (size_t)b * n4;

    float s = 0.0f;
    const int stride = gridDim.x * blockDim.x;
    for (int i = blockIdx.x * blockDim.x + threadIdx.x; i < n4; i += stride) {
        float4 v = __ldg(&p[i]);
        s += (v.x + v.y) + (v.z + v.w);
    }
    // handle tail (chw % 4) — not hit for this shape but keep correct
    if (blockIdx.x == 0 && threadIdx.x < (chw & 3)) {
        s += __ldg(im + (size_t)b * chw + (size_t)(n4 << 2) + threadIdx.x);
    }

    // warp reduce
    #pragma unroll
    for (int o = 16; o > 0; o >>= 1)
        s += __shfl_down_sync(0xffffffffu, s, o);

    __shared__ float warp_s[8];
    const int lane = threadIdx.x & 31;
    const int wid  = threadIdx.x >> 5;
    if (lane == 0) warp_s[wid] = s;
    __syncthreads();
    if (wid == 0) {
        s = (lane < (blockDim.x >> 5)) ? warp_s[lane] : 0.0f;
        #pragma unroll
        for (int o = 4; o > 0; o >>= 1)
            s += __shfl_down_sync(0xffffffffu, s, o);
        if (lane == 0) atomicAdd(&g_sum[b], (double)s);
    }
}

// Grid: (S, B) — one block per (batch b, output row oy). 256 threads, thread
// ox in [0,S) computes all C channels of output pixel (b, :, oy, ox).
__global__ void subwindow_kernel(const float* __restrict__ im,
                                 const float* __restrict__ pos,
                                 const float* __restrict__ szw,
                                 float* __restrict__ out,
                                 int C, int H, int W, int S, int chw) {
    const int b  = blockIdx.y;
    const int oy = blockIdx.x;
    const int ox = threadIdx.x;
    if (ox >= S) return;

    const float sz = __ldg(&szw[b]);
    const float px = __ldg(&pos[2 * b + 0]);
    const float py = __ldg(&pos[2 * b + 1]);

    const float avg = (float)(g_sum[b] / (double)chw);

    const float cc    = (sz + 1.0f) * 0.5f;
    const float xmin  = rintf(px - cc);          // jnp.round = half-to-even = rintf
    const float ymin  = rintf(py - cc);
    const float scale = sz / (float)S;
    const int   imax  = (int)fmaxf(sz - 1.0f, 0.0f);   // astype(int32): trunc

    // --- x axis (per thread) ---
    float srcx = ((float)ox + 0.5f) * scale - 0.5f;
    srcx = fmaxf(srcx, 0.0f);
    const float ix0f = floorf(srcx);
    const float fx   = srcx - ix0f;
    const int ix0 = min((int)ix0f, imax);
    const int ix1 = min(ix0 + 1, imax);

    // --- y axis (uniform across block; cheap to recompute) ---
    float srcy = ((float)oy + 0.5f) * scale - 0.5f;
    srcy = fmaxf(srcy, 0.0f);
    const float iy0f = floorf(srcy);
    const float fy   = srcy - iy0f;
    const int iy0 = min((int)iy0f, imax);
    const int iy1 = min(iy0 + 1, imax);

    // axis_coords: g = i + origin (float); valid = 0 <= g <= limit-1;
    // gi = clip(trunc(g), 0, limit-1)
    const float gx0 = (float)ix0 + xmin;
    const float gx1 = (float)ix1 + xmin;
    const float gy0 = (float)iy0 + ymin;
    const float gy1 = (float)iy1 + ymin;

    const bool vx0 = (gx0 >= 0.0f) && (gx0 <= (float)(W - 1));
    const bool vx1 = (gx1 >= 0.0f) && (gx1 <= (float)(W - 1));
    const bool vy0 = (gy0 >= 0.0f) && (gy0 <= (float)(H - 1));
    const bool vy1 = (gy1 >= 0.0f) && (gy1 <= (float)(H - 1));

    const int x0 = min(max((int)gx0, 0), W - 1);
    const int x1 = min(max((int)gx1, 0), W - 1);
    const int y0 = min(max((int)gy0, 0), H - 1);
    const int y1 = min(max((int)gy1, 0), H - 1);

    const bool m00 = vy0 && vx0;
    const bool m01 = vy0 && vx1;
    const bool m10 = vy1 && vx0;
    const bool m11 = vy1 && vx1;

    const size_t imgBase = (size_t)b * chw;
    const int hw = H * W;
    const int r0 = y0 * W, r1 = y1 * W;

    #pragma unroll 3
    for (int c = 0; c < 3; c++) {
        const float* __restrict__ ip = im + imgBase + (size_t)c * hw;
        float v00 = m00 ? __ldg(ip + r0 + x0) : avg;
        float v01 = m01 ? __ldg(ip + r0 + x1) : avg;
        float v10 = m10 ? __ldg(ip + r1 + x0) : avg;
        float v11 = m11 ? __ldg(ip + r1 + x1) : avg;

        float top = v00 * (1.0f - fx) + v01 * fx;
        float bot = v10 * (1.0f - fx) + v11 * fx;
        float res = top * (1.0f - fy) + bot * fy;

        out[((size_t)(b * C + c) * S + oy) * S + ox] = res;
    }
}

extern "C" void kernel_launch(void* const* d_in, const int* in_sizes, int n_in,
                              void* d_out, int out_size) {
    const float* im  = (const float*)d_in[0];
    const float* pos = (const float*)d_in[1];
    const float* szw = (const float*)d_in[2];
    float* out = (float*)d_out;

    const int B   = in_sizes[1] / 2;          // pos is (B,2)
    const int chw = in_sizes[0] / B;          // C*H*W per image
    const int C = 3;
    const int H = 720;
    const int W = 1280;
    // out_size = B*C*S*S -> S
    int S = (int)(sqrtf((float)(out_size / (B * C))) + 0.5f);

    zero_sums_kernel<<<1, MAX_B>>>();
    reduce_mean_kernel<<<dim3(64, B), 256>>>(im, chw);
    subwindow_kernel<<<dim3(S, B), 256>>>(im, pos, szw, out, C, H, W, S, chw);
}

// round 3
// speedup vs baseline: 1.0047x; 1.0047x over previous
#include <cuda_runtime.h>
#include <math.h>

#define MAX_B 64
#define RED_PER_IMG 64   // reduce blocks per image

// Partial sums: g_part[b*RED_PER_IMG + slice]
__device__ float g_part[MAX_B * RED_PER_IMG];

// ---------------------------------------------------------------------------
// Fused kernel: blocks [0, nRed) compute mean partials; blocks [nRed, ...)
// compute the bilinear subwindow with invalid (out-of-image) taps as ZERO.
// The avg contribution is added later by fixup_kernel (exact decomposition:
// result = base + avg * coeff).
// ---------------------------------------------------------------------------
__global__ void fused_kernel(const float* __restrict__ im,
                             const float* __restrict__ pos,
                             const float* __restrict__ szw,
                             float* __restrict__ out,
                             int B, int C, int H, int W, int S, int chw,
                             int nRed) {
    if ((int)blockIdx.x < nRed) {
        // ---------------- mean partial reduction ----------------
        const int r     = blockIdx.x;
        const int b     = r >> 6;            // RED_PER_IMG = 64
        const int slice = r & 63;
        const int n4    = chw >> 2;
        const float4* __restrict__ p =
            reinterpret_cast<const float4*>(im) + (size_t)b * n4;

        float s = 0.0f;
        const int stride = RED_PER_IMG * 256;
        #pragma unroll 4
        for (int i = slice * 256 + threadIdx.x; i < n4; i += stride) {
            float4 v = __ldg(&p[i]);
            s += (v.x + v.y) + (v.z + v.w);
        }
        if (slice == 0 && threadIdx.x < (chw & 3))
            s += __ldg(im + (size_t)b * chw + (size_t)(n4 << 2) + threadIdx.x);

        #pragma unroll
        for (int o = 16; o > 0; o >>= 1)
            s += __shfl_down_sync(0xffffffffu, s, o);

        __shared__ float warp_s[8];
        const int lane = threadIdx.x & 31;
        const int wid  = threadIdx.x >> 5;
        if (lane == 0) warp_s[wid] = s;
        __syncthreads();
        if (wid == 0) {
            s = (lane < 8) ? warp_s[lane] : 0.0f;
            #pragma unroll
            for (int o = 4; o > 0; o >>= 1)
                s += __shfl_down_sync(0xffffffffu, s, o);
            if (lane == 0) g_part[r] = s;
        }
        return;
    }

    // ---------------- subwindow base (avg-free) ----------------
    const int q  = (int)blockIdx.x - nRed;
    const int oy = q / B;
    const int b  = q - oy * B;
    const int ox = threadIdx.x;
    if (ox >= S) return;

    const float sz = __ldg(&szw[b]);
    const float px = __ldg(&pos[2 * b + 0]);
    const float py = __ldg(&pos[2 * b + 1]);

    const float cc    = (sz + 1.0f) * 0.5f;
    const float xmin  = rintf(px - cc);          // jnp.round = half-to-even
    const float ymin  = rintf(py - cc);
    const float scale = sz / (float)S;
    const int   imax  = (int)fmaxf(sz - 1.0f, 0.0f);

    float srcx = fmaxf(((float)ox + 0.5f) * scale - 0.5f, 0.0f);
    const float ix0f = floorf(srcx);
    const float fx   = srcx - ix0f;
    const int ix0 = min((int)ix0f, imax);
    const int ix1 = min(ix0 + 1, imax);

    float srcy = fmaxf(((float)oy + 0.5f) * scale - 0.5f, 0.0f);
    const float iy0f = floorf(srcy);
    const float fy   = srcy - iy0f;
    const int iy0 = min((int)iy0f, imax);
    const int iy1 = min(iy0 + 1, imax);

    const float gx0 = (float)ix0 + xmin;
    const float gx1 = (float)ix1 + xmin;
    const float gy0 = (float)iy0 + ymin;
    const float gy1 = (float)iy1 + ymin;

    const bool vx0 = (gx0 >= 0.0f) && (gx0 <= (float)(W - 1));
    const bool vx1 = (gx1 >= 0.0f) && (gx1 <= (float)(W - 1));
    const bool vy0 = (gy0 >= 0.0f) && (gy0 <= (float)(H - 1));
    const bool vy1 = (gy1 >= 0.0f) && (gy1 <= (float)(H - 1));

    const int x0 = min(max((int)gx0, 0), W - 1);
    const int x1 = min(max((int)gx1, 0), W - 1);
    const int y0 = min(max((int)gy0, 0), H - 1);
    const int y1 = min(max((int)gy1, 0), H - 1);

    const bool m00 = vy0 && vx0;
    const bool m01 = vy0 && vx1;
    const bool m10 = vy1 && vx0;
    const bool m11 = vy1 && vx1;

    const size_t imgBase = (size_t)b * chw;
    const int hw = H * W;
    const int r0 = y0 * W, r1 = y1 * W;

    #pragma unroll 3
    for (int c = 0; c < 3; c++) {
        const float* __restrict__ ip = im + imgBase + (size_t)c * hw;
        float v00 = m00 ? __ldg(ip + r0 + x0) : 0.0f;
        float v01 = m01 ? __ldg(ip + r0 + x1) : 0.0f;
        float v10 = m10 ? __ldg(ip + r1 + x0) : 0.0f;
        float v11 = m11 ? __ldg(ip + r1 + x1) : 0.0f;

        float top = v00 * (1.0f - fx) + v01 * fx;
        float bot = v10 * (1.0f - fx) + v11 * fx;
        float res = top * (1.0f - fy) + bot * fy;

        out[((size_t)(b * C + c) * S + oy) * S + ox] = res;
    }
}

// ---------------------------------------------------------------------------
// Fixup: recompute masks/weights (ALU only), add avg*coeff where any tap was
// out of image. No image reads; out touched only at border pixels.
// ---------------------------------------------------------------------------
__global__ void fixup_kernel(const float* __restrict__ pos,
                             const float* __restrict__ szw,
                             float* __restrict__ out,
                             int B, int C, int H, int W, int S, int chw) {
    const int b  = blockIdx.y;
    const int oy = blockIdx.x;

    __shared__ float sh_avg;
    {
        __shared__ float sh[RED_PER_IMG];
        if (threadIdx.x < RED_PER_IMG)
            sh[threadIdx.x] = g_part[b * RED_PER_IMG + threadIdx.x];
        __syncthreads();
        if (threadIdx.x < 32) {
            float v = sh[threadIdx.x] + sh[threadIdx.x + 32];
            #pragma unroll
            for (int o = 16; o > 0; o >>= 1)
                v += __shfl_down_sync(0xffffffffu, v, o);
            if (threadIdx.x == 0) sh_avg = v / (float)chw;
        }
        __syncthreads();
    }
    const float avg = sh_avg;

    const int ox = threadIdx.x;
    if (ox >= S) return;

    const float sz = __ldg(&szw[b]);
    const float px = __ldg(&pos[2 * b + 0]);
    const float py = __ldg(&pos[2 * b + 1]);

    const float cc    = (sz + 1.0f) * 0.5f;
    const float xmin  = rintf(px - cc);
    const float ymin  = rintf(py - cc);
    const float scale = sz / (float)S;
    const int   imax  = (int)fmaxf(sz - 1.0f, 0.0f);

    float srcx = fmaxf(((float)ox + 0.5f) * scale - 0.5f, 0.0f);
    const float ix0f = floorf(srcx);
    const float fx   = srcx - ix0f;
    const int ix0 = min((int)ix0f, imax);
    const int ix1 = min(ix0 + 1, imax);

    float srcy = fmaxf(((float)oy + 0.5f) * scale - 0.5f, 0.0f);
    const float iy0f = floorf(srcy);
    const float fy   = srcy - iy0f;
    const int iy0 = min((int)iy0f, imax);
    const int iy1 = min(iy0 + 1, imax);

    const float gx0 = (float)ix0 + xmin;
    const float gx1 = (float)ix1 + xmin;
    const float gy0 = (float)iy0 + ymin;
    const float gy1 = (float)iy1 + ymin;

    const bool vy0 = (gy0 >= 0.0f) && (gy0 <= (float)(H - 1));
    const bool vy1 = (gy1 >= 0.0f) && (gy1 <= (float)(H - 1));
    const bool vx0 = (gx0 >= 0.0f) && (gx0 <= (float)(W - 1));
    const bool vx1 = (gx1 >= 0.0f) && (gx1 <= (float)(W - 1));

    const bool m00 = vy0 && vx0;
    const bool m01 = vy0 && vx1;
    const bool m10 = vy1 && vx0;
    const bool m11 = vy1 && vx1;

    // coeff mirrors the bilinear nesting with (1 - mask) in place of values
    const float ca = (m00 ? 0.0f : (1.0f - fx)) + (m01 ? 0.0f : fx);
    const float cb = (m10 ? 0.0f : (1.0f - fx)) + (m11 ? 0.0f : fx);
    const float coeff = ca * (1.0f - fy) + cb * fy;

    if (coeff != 0.0f) {
        const float add = avg * coeff;
        #pragma unroll 3
        for (int c = 0; c < 3; c++) {
            size_t idx = ((size_t)(b * C + c) * S + oy) * S + ox;
            out[idx] += add;
        }
    }
}

extern "C" void kernel_launch(void* const* d_in, const int* in_sizes, int n_in,
                              void* d_out, int out_size) {
    const float* im  = (const float*)d_in[0];
    const float* pos = (const float*)d_in[1];
    const float* szw = (const float*)d_in[2];
    float* out = (float*)d_out;

    const int B   = in_sizes[1] / 2;
    const int chw = in_sizes[0] / B;
    const int C = 3;
    const int H = 720;
    const int W = 1280;
    int S = (int)(sqrtf((float)(out_size / (B * C))) + 0.5f);

    const int nRed = RED_PER_IMG * B;                 // 2048 reduce blocks
    const int nTot = nRed + S * B;                    // + 8160 subwindow blocks

    fused_kernel<<<nTot, 256>>>(im, pos, szw, out, B, C, H, W, S, chw, nRed);
    fixup_kernel<<<dim3(S, B), 256>>>(pos, szw, out, B, C, H, W, S, chw);
}